// round 12
// baseline (speedup 1.0000x reference)
#include <cuda_runtime.h>
#include <cstdint>
#include <math.h>

#define B_   2
#define S_   2048
#define DM_  1024
#define H_   16
#define DH_  64
#define BSN_ (B_ * S_)     // 4096 rows
#define HB_  (H_ * B_)     // 32 (head,batch) pairs
#define PLANE_ (HB_ * S_ * DH_)

__device__ float g_qkv[3 * PLANE_];
__device__ float g_apack[3 * PLANE_];
__device__ float g_attp[PLANE_];
__device__ float g_wpack[4 * DM_ * DM_];
__device__ int   g_sync[16];    // [0] ticket counter, [1..8] per-group flags

// ---------------------------------------------------------------------------
// helpers
// ---------------------------------------------------------------------------
__device__ __forceinline__ uint32_t smem_u32(const void* p) {
    uint32_t a;
    asm("{ .reg .u64 t; cvta.to.shared.u64 t, %1; cvt.u32.u64 %0, t; }"
        : "=r"(a) : "l"(p));
    return a;
}
__device__ __forceinline__ uint32_t to_tf32(float x) {
    uint32_t r;
    asm("cvt.rna.tf32.f32 %0, %1;" : "=r"(r) : "f"(x));
    return r;
}
__device__ __forceinline__ void mma_16n8k8(float* c, const uint32_t* a, const uint32_t* b) {
    asm volatile(
        "mma.sync.aligned.m16n8k8.row.col.f32.tf32.tf32.f32 "
        "{%0,%1,%2,%3}, {%4,%5,%6,%7}, {%8,%9}, {%0,%1,%2,%3};\n"
        : "+f"(c[0]), "+f"(c[1]), "+f"(c[2]), "+f"(c[3])
        : "r"(a[0]), "r"(a[1]), "r"(a[2]), "r"(a[3]), "r"(b[0]), "r"(b[1]));
}
#define CP16(dst, src) \
    asm volatile("{ .reg .u64 gp; cvta.to.global.u64 gp, %1; " \
                 "cp.async.ca.shared.global [%0], [gp], 16; }" \
                 :: "r"(dst), "l"(src) : "memory")
#define CP_COMMIT() asm volatile("cp.async.commit_group;" ::: "memory")
#define CP_WAIT1()  asm volatile("cp.async.wait_group 1;" ::: "memory")

// ---------------------------------------------------------------------------
// zero_sync: graph-safe reset of the ticket/flag block (replaces memsetAsync)
// ---------------------------------------------------------------------------
__global__ void zero_sync(int* __restrict__ syncb) {
    if (threadIdx.x < 16) syncb[threadIdx.x] = 0;
}

// ---------------------------------------------------------------------------
// pack_inputs / pack_w : unchanged from R10 (validated)
// ---------------------------------------------------------------------------
__global__ __launch_bounds__(256) void pack_inputs(
    const float* __restrict__ Q, const float* __restrict__ K,
    const float* __restrict__ V, float* __restrict__ Ap)
{
    __shared__ float s[128 * 36];
    const int z = blockIdx.z, cx = blockIdx.x, my = blockIdx.y;
    const int tid = threadIdx.x;
    const float* A = z == 0 ? Q : (z == 1 ? K : V);
#pragma unroll
    for (int j = 0; j < 4; j++) {
        const int idx = tid + j * 256;
        const int r = idx >> 3, c4 = (idx & 7) * 4;
        *(float4*)&s[r * 36 + c4] =
            *(const float4*)&A[(size_t)(my * 128 + r) * DM_ + cx * 32 + c4];
    }
    __syncthreads();
    float* dst = Ap + (size_t)z * PLANE_ + ((size_t)my * 32 + cx) * 4096;
#pragma unroll
    for (int j = 0; j < 4; j++) {
        const int ci = tid + j * 256;
        const int kt = ci >> 8, mtg = (ci >> 5) & 7, ln = ci & 31;
        const int r0 = mtg * 16 + (ln >> 2), c0 = kt * 8 + (ln & 3);
        uint4 o;
        o.x = to_tf32(s[r0 * 36 + c0]);
        o.y = to_tf32(s[(r0 + 8) * 36 + c0]);
        o.z = to_tf32(s[r0 * 36 + c0 + 4]);
        o.w = to_tf32(s[(r0 + 8) * 36 + c0 + 4]);
        *(uint4*)&dst[ci * 4] = o;
    }
}

__global__ __launch_bounds__(256) void pack_w(
    const float* __restrict__ Wq, const float* __restrict__ Wk,
    const float* __restrict__ Wv, const float* __restrict__ Wo,
    float* __restrict__ Wp)
{
    __shared__ float s[32 * 132];
    const int z = blockIdx.z, cx = blockIdx.x, nt8 = blockIdx.y;
    const int tid = threadIdx.x;
    if (z < 3) {
        const float* W = z == 0 ? Wq : (z == 1 ? Wk : Wv);
        const int h0 = nt8 * 2;
#pragma unroll
        for (int j = 0; j < 4; j++) {
            const int idx = tid + j * 256;
            const int k = idx >> 5, hi = (idx >> 4) & 1, jj = (idx & 15) * 4;
            *(float4*)&s[k * 132 + hi * 64 + jj] =
                *(const float4*)&W[(size_t)(h0 + hi) * (DM_ * DH_) +
                                   (size_t)(cx * 32 + k) * DH_ + jj];
        }
    } else {
#pragma unroll
        for (int j = 0; j < 4; j++) {
            const int idx = tid + j * 256;
            const int k = idx >> 5, nn = (idx & 31) * 4;
            *(float4*)&s[k * 132 + nn] =
                *(const float4*)&Wo[(size_t)(cx * 32 + k) * DM_ + nt8 * 128 + nn];
        }
    }
    __syncthreads();
    float* dst = Wp + (size_t)z * DM_ * DM_ + ((size_t)nt8 * 32 + cx) * 4096;
#pragma unroll
    for (int j = 0; j < 4; j++) {
        const int ci = tid + j * 256;
        const int kt = ci >> 8, ng = (ci >> 5) & 7, ln = ci & 31;
        const int ke = kt * 8 + (ln & 3), ne = ng * 16 + (ln >> 2);
        uint4 o;
        o.x = to_tf32(s[ke * 132 + ne]);
        o.y = to_tf32(s[(ke + 4) * 132 + ne]);
        o.z = to_tf32(s[ke * 132 + ne + 8]);
        o.w = to_tf32(s[(ke + 4) * 132 + ne + 8]);
        *(uint4*)&dst[ci * 4] = o;
    }
}

// ---------------------------------------------------------------------------
// GEMM tile body (R10 gemm_body, mtile/ntile as params)
// ---------------------------------------------------------------------------
#define STGB 32768
#define GEMM_SMEM (3 * STGB)   // 98304

__device__ __noinline__ void gemm_tile(
    const float* __restrict__ Ap, const float* __restrict__ Bp,
    const float* __restrict__ bias, float* __restrict__ out,
    const int mode, const int mtile, const int ntile,
    char* smraw, const uint32_t sb)
{
    const int tid = threadIdx.x, lane = tid & 31, wid = tid >> 5;
    const int g = lane >> 2, qd = lane & 3;
    const int wm = wid & 1, wn = wid >> 1;
    const int m0 = mtile * 128, n0 = ntile * 128;

    const float* Ab = Ap + (size_t)mtile * 32 * 4096;
    const float* Bb = Bp + (size_t)ntile * 32 * 4096;

    float acc[4][4][4];
#pragma unroll
    for (int i = 0; i < 4; i++)
#pragma unroll
        for (int j = 0; j < 4; j++)
#pragma unroll
            for (int k = 0; k < 4; k++) acc[i][j][k] = 0.f;

#define GLOAD(c, s) do {                                                      \
    const uint32_t abase = sb + (s) * STGB;                                   \
    const uint32_t bbase = abase + 16384;                                     \
    const float* asrc = Ab + (size_t)(c) * 4096;                              \
    const float* bsrc = Bb + (size_t)(c) * 4096;                              \
    _Pragma("unroll")                                                         \
    for (int j = 0; j < 4; j++) {                                             \
        const int u = tid + j * 256;                                          \
        CP16(abase + u * 16, asrc + u * 4);                                   \
        CP16(bbase + u * 16, bsrc + u * 4);                                   \
    }                                                                         \
    CP_COMMIT();                                                              \
} while (0)

    GLOAD(0, 0);
    GLOAD(1, 1);

    for (int c = 0; c < 32; c++) {
        const int s = c - (c / 3) * 3;
        int s2 = s + 2; if (s2 >= 3) s2 -= 3;
        CP_WAIT1();
        __syncthreads();
        if (c < 30) GLOAD(c + 2, s2); else CP_COMMIT();

        const uint4* as = (const uint4*)(smraw + s * STGB);
        const uint4* bs = as + 1024;
#pragma unroll
        for (int kt = 0; kt < 4; kt++) {
            uint32_t af[4][4];
#pragma unroll
            for (int mt = 0; mt < 4; mt++) {
                uint4 v = as[(kt * 8 + wm * 4 + mt) * 32 + lane];
                af[mt][0] = v.x; af[mt][1] = v.y; af[mt][2] = v.z; af[mt][3] = v.w;
            }
            uint32_t bf[4][2];
#pragma unroll
            for (int p = 0; p < 2; p++) {
                uint4 v = bs[(kt * 8 + wn * 2 + p) * 32 + lane];
                bf[2 * p][0] = v.x; bf[2 * p][1] = v.y;
                bf[2 * p + 1][0] = v.z; bf[2 * p + 1][1] = v.w;
            }
#pragma unroll
            for (int mt = 0; mt < 4; mt++)
#pragma unroll
                for (int nt = 0; nt < 4; nt++)
                    mma_16n8k8(acc[mt][nt], af[mt], bf[nt]);
        }
    }
#undef GLOAD

#pragma unroll
    for (int mt = 0; mt < 4; mt++) {
#pragma unroll
        for (int nt = 0; nt < 4; nt++) {
            const int mb = m0 + wm * 64 + mt * 16 + g;
            const int nb = n0 + wn * 32 + nt * 8 + 2 * qd;
            if (mode == 0) {
                float2 v01, v23;
                v01.x = acc[mt][nt][0] + bias[nb];
                v01.y = acc[mt][nt][1] + bias[nb + 1];
                v23.x = acc[mt][nt][2] + bias[nb];
                v23.y = acc[mt][nt][3] + bias[nb + 1];
                *(float2*)&out[(size_t)mb * DM_ + nb] = v01;
                *(float2*)&out[(size_t)(mb + 8) * DM_ + nb] = v23;
            } else if (mode == 1) {
                float2 v01, v23;
                v01.x = __uint_as_float(to_tf32(acc[mt][nt][0] + bias[nb]));
                v01.y = __uint_as_float(to_tf32(acc[mt][nt][1] + bias[nb + 1]));
                v23.x = __uint_as_float(to_tf32(acc[mt][nt][2] + bias[nb]));
                v23.y = __uint_as_float(to_tf32(acc[mt][nt][3] + bias[nb + 1]));
                const size_t base = (size_t)(nb >> 6) * ((size_t)BSN_ * DH_) + (nb & 63);
                *(float2*)&out[base + (size_t)mb * DH_] = v01;
                *(float2*)&out[base + (size_t)(mb + 8) * DH_] = v23;
            } else {
#pragma unroll
                for (int e = 0; e < 4; e++) {
                    const int m = mb + ((e & 2) ? 8 : 0);
                    const int n = nb + (e & 1);
                    const float val =
                        __uint_as_float(to_tf32(acc[mt][nt][e] + bias[n]));
                    const int sidx = m & 2047, d = n & 63;
                    const int hb = (n >> 6) * 2 + (m >> 11);
                    const int sl = sidx & 63;
                    const size_t base = (size_t)(hb * 32 + (sidx >> 6)) * 4096;
                    size_t off;
                    if (mode == 2)
                        off = base +
                              (((d >> 3) * 4 + (sl >> 4)) * 32 +
                               (sl & 7) * 4 + (d & 3)) * 4 +
                              ((sl >> 3) & 1) * 2 + ((d >> 2) & 1);
                    else
                        off = base +
                              (((sl >> 3) * 4 + (d >> 4)) * 32 +
                               (d & 7) * 4 + (sl & 3)) * 4 +
                              ((d >> 3) & 1) * 2 + ((sl >> 2) & 1);
                    out[off] = val;
                }
            }
        }
    }
}

// ---------------------------------------------------------------------------
// Attention tile body (R10 attn_mma, qb/hb as params)
// ---------------------------------------------------------------------------
__device__ __noinline__ void attn_tile(
    const float* __restrict__ Q, const float* __restrict__ K,
    const float* __restrict__ V, float* __restrict__ Op,
    const int qb, const int hb, float* sm, const uint32_t sb)
{
    const int tid = threadIdx.x, lane = tid & 31, wid = tid >> 5;
    const int g = lane >> 2, qd = lane & 3;
    float* Pw = sm + 16384 + wid * 1024;

    const int q0 = qb * 128;
    const float* Qg = Q + (size_t)hb * (S_ * DH_);
    const float* Kg = K + (size_t)hb * (S_ * DH_);
    const float* Vg = V + (size_t)hb * (S_ * DH_);

    uint32_t qf[8][4];
    {
        const float* r0 = Qg + (size_t)(q0 + wid * 16 + g) * DH_ + qd;
        const float* r8 = r0 + 8 * DH_;
#pragma unroll
        for (int kt = 0; kt < 8; kt++) {
            qf[kt][0] = __float_as_uint(r0[kt * 8] * 0.125f);
            qf[kt][1] = __float_as_uint(r8[kt * 8] * 0.125f);
            qf[kt][2] = __float_as_uint(r0[kt * 8 + 4] * 0.125f);
            qf[kt][3] = __float_as_uint(r8[kt * 8 + 4] * 0.125f);
        }
    }

#define KVLOAD(t, st) do {                                                    \
    const uint32_t kb = sb + (st) * 32768;                                    \
    const uint32_t vb = kb + 16384;                                           \
    const float* ksrc = Kg + (size_t)(t) * 4096;                              \
    const float* vsrc = Vg + (size_t)(t) * 4096;                              \
    _Pragma("unroll")                                                         \
    for (int j = 0; j < 4; j++) {                                             \
        const int u = tid + j * 256;                                          \
        CP16(kb + u * 16, ksrc + u * 4);                                      \
        CP16(vb + u * 16, vsrc + u * 4);                                      \
    }                                                                         \
    CP_COMMIT();                                                              \
} while (0)

    float accO[8][4];
#pragma unroll
    for (int nt = 0; nt < 8; nt++)
#pragma unroll
        for (int i = 0; i < 4; i++) accO[nt][i] = 0.f;
    float m0 = -1e30f, m1 = -1e30f, l0 = 0.f, l1 = 0.f;

    KVLOAD(0, 0);
    KVLOAD(1, 1);

    for (int t = 0; t < 32; t++) {
        const int st = t & 1;
        CP_WAIT1();
        __syncthreads();
        const uint4* K4 = (const uint4*)(sm + st * 8192);
        const uint4* V4 = (const uint4*)(sm + st * 8192 + 4096);

        float s[8][4];
#pragma unroll
        for (int nt = 0; nt < 8; nt++)
#pragma unroll
            for (int i = 0; i < 4; i++) s[nt][i] = 0.f;
#pragma unroll
        for (int kt = 0; kt < 8; kt++) {
#pragma unroll
            for (int np = 0; np < 4; np++) {
                uint4 v = K4[(kt * 4 + np) * 32 + lane];
                uint32_t b0[2] = {v.x, v.y};
                mma_16n8k8(s[2 * np], qf[kt], b0);
                uint32_t b1[2] = {v.z, v.w};
                mma_16n8k8(s[2 * np + 1], qf[kt], b1);
            }
        }

        float mn0 = m0, mn1 = m1;
#pragma unroll
        for (int nt = 0; nt < 8; nt++) {
            mn0 = fmaxf(mn0, fmaxf(s[nt][0], s[nt][1]));
            mn1 = fmaxf(mn1, fmaxf(s[nt][2], s[nt][3]));
        }
        mn0 = fmaxf(mn0, __shfl_xor_sync(0xffffffffu, mn0, 1));
        mn0 = fmaxf(mn0, __shfl_xor_sync(0xffffffffu, mn0, 2));
        mn1 = fmaxf(mn1, __shfl_xor_sync(0xffffffffu, mn1, 1));
        mn1 = fmaxf(mn1, __shfl_xor_sync(0xffffffffu, mn1, 2));
        const float c0 = __expf(m0 - mn0), c1 = __expf(m1 - mn1);
        m0 = mn0; m1 = mn1;
        float rs0 = 0.f, rs1 = 0.f;
#pragma unroll
        for (int nt = 0; nt < 8; nt++) {
            const float p0 = __expf(s[nt][0] - mn0);
            const float p1 = __expf(s[nt][1] - mn0);
            const float p2 = __expf(s[nt][2] - mn1);
            const float p3 = __expf(s[nt][3] - mn1);
            rs0 += p0 + p1;
            rs1 += p2 + p3;
            float* ch = Pw + nt * 128 + g * 16 + ((qd >= 2) ? 2 : 0);
            const int qa = (2 * qd) & 3, qb2 = (2 * qd + 1) & 3;
            ch[qa * 4]      = __uint_as_float(to_tf32(p0));
            ch[qb2 * 4]     = __uint_as_float(to_tf32(p1));
            ch[qa * 4 + 1]  = __uint_as_float(to_tf32(p2));
            ch[qb2 * 4 + 1] = __uint_as_float(to_tf32(p3));
        }
        rs0 += __shfl_xor_sync(0xffffffffu, rs0, 1);
        rs0 += __shfl_xor_sync(0xffffffffu, rs0, 2);
        rs1 += __shfl_xor_sync(0xffffffffu, rs1, 1);
        rs1 += __shfl_xor_sync(0xffffffffu, rs1, 2);
        l0 = l0 * c0 + rs0;
        l1 = l1 * c1 + rs1;
#pragma unroll
        for (int nt = 0; nt < 8; nt++) {
            accO[nt][0] *= c0; accO[nt][1] *= c0;
            accO[nt][2] *= c1; accO[nt][3] *= c1;
        }
        __syncwarp();

        const uint4* P4 = (const uint4*)Pw;
#pragma unroll
        for (int kt = 0; kt < 8; kt++) {
            uint4 av = P4[kt * 32 + lane];
            uint32_t a[4] = {av.x, av.y, av.z, av.w};
#pragma unroll
            for (int np = 0; np < 4; np++) {
                uint4 v = V4[(kt * 4 + np) * 32 + lane];
                uint32_t b0[2] = {v.x, v.y};
                mma_16n8k8(accO[2 * np], a, b0);
                uint32_t b1[2] = {v.z, v.w};
                mma_16n8k8(accO[2 * np + 1], a, b1);
            }
        }
        __syncthreads();
        if (t < 30) KVLOAD(t + 2, st); else CP_COMMIT();
    }
#undef KVLOAD

    const float i0 = 1.f / l0, i1 = 1.f / l1;
    const int mrow = 8 * qb + wid;
    const int mtg = mrow >> 4;
    const int rr = mrow & 15;
    const int halfm = rr >> 3, gfrag = rr & 7;
#pragma unroll
    for (int nt = 0; nt < 8; nt++) {
        float vals[4];
        vals[0] = accO[nt][0] * i0;
        vals[1] = accO[nt][1] * i0;
        vals[2] = accO[nt][2] * i1;
        vals[3] = accO[nt][3] * i1;
        const int kbase = g * 64 + nt * 8 + 2 * qd;
#pragma unroll
        for (int e = 0; e < 4; e++) {
            const int k = kbase + (e & 1) + (e >> 1) * 512;
            const int chunk = k >> 5;
            const int kt = (k >> 3) & 3;
            const int q4 = k & 7;
            const int qp = q4 >> 2, qdf = q4 & 3;
            const int lane2 = gfrag * 4 + qdf;
            const int word = halfm + 2 * qp;
            const size_t off = ((size_t)(hb * 32 + chunk)) * 4096 +
                               ((kt * 8 + mtg) * 32 + lane2) * 4 + word;
            Op[off] = __uint_as_float(to_tf32(vals[e]));
        }
    }
}

// ---------------------------------------------------------------------------
// Fused persistent kernel: gemm_qkv tiles + attention tiles from one
// dependency-ordered ticket queue.
// Queue: for k in 0..7:  96 gemm tickets (z,mt for ntile=k)  then
//                        64 attn tickets (hb=4k..4k+3, qb 0..15).
// Deadlock-free at ANY residency: attn tickets of group k are only ever
// dispensed after all 96 gemm tickets of group k are held by running CTAs.
// ---------------------------------------------------------------------------
#define N_TICKETS 1280

__global__ __launch_bounds__(256, 2) void fused_qkv_attn(
    const float* __restrict__ Apack, const float* __restrict__ Wp,
    const float* __restrict__ bq, const float* __restrict__ bk,
    const float* __restrict__ bv,
    float* __restrict__ qkv, float* __restrict__ attp, int* __restrict__ syncb)
{
    extern __shared__ __align__(16) float sm[];
    __shared__ int s_ticket;
    const uint32_t sb = smem_u32(sm);
    const int tid = threadIdx.x;

    for (;;) {
        if (tid == 0) s_ticket = atomicAdd(&syncb[0], 1);
        __syncthreads();
        const int t = s_ticket;
        if (t >= N_TICKETS) break;

        const int k = t / 160, r = t - k * 160;
        if (r < 96) {
            const int z = r >> 5, mt = r & 31;
            const float* bias = z == 0 ? bq : (z == 1 ? bk : bv);
            const int mode = z == 0 ? 1 : (z == 1 ? 2 : 3);
            gemm_tile(Apack + (size_t)z * PLANE_, Wp + (size_t)z * DM_ * DM_,
                      bias, qkv + (size_t)z * PLANE_, mode, mt, k,
                      (char*)sm, sb);
            __threadfence();
            __syncthreads();
            if (tid == 0) atomicAdd(&syncb[1 + k], 1);
        } else {
            const int a = r - 96;
            const int hb = k * 4 + (a >> 4), qb = a & 15;
            if (tid == 0) {
                int v;
                do {
                    asm volatile("ld.acquire.gpu.b32 %0, [%1];"
                                 : "=r"(v) : "l"(&syncb[1 + k]) : "memory");
                    if (v < 96) __nanosleep(256);
                } while (v < 96);
            }
            __syncthreads();
            attn_tile(qkv, qkv + PLANE_, qkv + 2 * PLANE_, attp, qb, hb, sm, sb);
        }
    }
}

// ---------------------------------------------------------------------------
// Output GEMM (separate launch; needs all heads)
// ---------------------------------------------------------------------------
__global__ __launch_bounds__(256, 2) void gemm_o(
    const float* __restrict__ Apack, const float* __restrict__ Bp,
    const float* __restrict__ bias, float* __restrict__ out)
{
    extern __shared__ __align__(16) char smraw[];
    gemm_tile(Apack, Bp, bias, out, 0, blockIdx.y, blockIdx.x,
              smraw, smem_u32(smraw));
}

// ---------------------------------------------------------------------------
extern "C" void kernel_launch(void* const* d_in, const int* in_sizes, int n_in,
                              void* d_out, int out_size)
{
    const float* query = (const float*)d_in[0];
    const float* key_  = (const float*)d_in[1];
    const float* value = (const float*)d_in[2];
    const float* Wq    = (const float*)d_in[3];
    const float* bq    = (const float*)d_in[4];
    const float* Wk    = (const float*)d_in[5];
    const float* bk    = (const float*)d_in[6];
    const float* Wv    = (const float*)d_in[7];
    const float* bv    = (const float*)d_in[8];
    const float* Wo    = (const float*)d_in[9];
    const float* bo    = (const float*)d_in[10];
    float* out = (float*)d_out;

    float *qkv, *apack, *attp, *wpack;
    int* syncb;
    cudaGetSymbolAddress((void**)&qkv, g_qkv);
    cudaGetSymbolAddress((void**)&apack, g_apack);
    cudaGetSymbolAddress((void**)&attp, g_attp);
    cudaGetSymbolAddress((void**)&wpack, g_wpack);
    cudaGetSymbolAddress((void**)&syncb, g_sync);

    cudaFuncSetAttribute(fused_qkv_attn, cudaFuncAttributeMaxDynamicSharedMemorySize, GEMM_SMEM);
    cudaFuncSetAttribute(gemm_o, cudaFuncAttributeMaxDynamicSharedMemorySize, GEMM_SMEM);

    zero_sync<<<1, 32>>>(syncb);

    pack_w<<<dim3(32, 8, 4), 256>>>(Wq, Wk, Wv, Wo, wpack);
    pack_inputs<<<dim3(32, 32, 3), 256>>>(query, key_, value, apack);

    fused_qkv_attn<<<296, 256, GEMM_SMEM>>>(apack, wpack, bq, bk, bv,
                                            qkv, attp, syncb);

    gemm_o<<<dim3(8, 32), 256, GEMM_SMEM>>>(attp, wpack + (size_t)3 * DM_ * DM_,
                                            bo, out);
}

// round 13
// speedup vs baseline: 1.2346x; 1.2346x over previous
#include <cuda_runtime.h>
#include <cstdint>
#include <math.h>

#define B_   2
#define S_   2048
#define DM_  1024
#define H_   16
#define DH_  64
#define BSN_ (B_ * S_)     // 4096 rows
#define HB_  (H_ * B_)     // 32 (head,batch) pairs
#define PLANE_ (HB_ * S_ * DH_)

// g_qkv planes: Q row-major [H][B][S][DH]; K packed QK-B-frag blocks;
//               V packed PV-B-frag blocks (16KB per (hb, 64-row tile)).
__device__ float g_qkv[3 * PLANE_];
__device__ float g_apack[3 * PLANE_];
__device__ float g_attp[PLANE_];
__device__ float g_wpack[4 * DM_ * DM_];

// ---------------------------------------------------------------------------
// helpers
// ---------------------------------------------------------------------------
__device__ __forceinline__ uint32_t smem_u32(const void* p) {
    uint32_t a;
    asm("{ .reg .u64 t; cvta.to.shared.u64 t, %1; cvt.u32.u64 %0, t; }"
        : "=r"(a) : "l"(p));
    return a;
}
__device__ __forceinline__ uint32_t to_tf32(float x) {
    uint32_t r;
    asm("cvt.rna.tf32.f32 %0, %1;" : "=r"(r) : "f"(x));
    return r;
}
__device__ __forceinline__ void mma_16n8k8(float* c, const uint32_t* a, const uint32_t* b) {
    asm volatile(
        "mma.sync.aligned.m16n8k8.row.col.f32.tf32.tf32.f32 "
        "{%0,%1,%2,%3}, {%4,%5,%6,%7}, {%8,%9}, {%0,%1,%2,%3};\n"
        : "+f"(c[0]), "+f"(c[1]), "+f"(c[2]), "+f"(c[3])
        : "r"(a[0]), "r"(a[1]), "r"(a[2]), "r"(a[3]), "r"(b[0]), "r"(b[1]));
}
#define CP16(dst, src) \
    asm volatile("{ .reg .u64 gp; cvta.to.global.u64 gp, %1; " \
                 "cp.async.ca.shared.global [%0], [gp], 16; }" \
                 :: "r"(dst), "l"(src) : "memory")
#define CP_COMMIT() asm volatile("cp.async.commit_group;" ::: "memory")
#define CP_WAIT1()  asm volatile("cp.async.wait_group 1;" ::: "memory")

// ---------------------------------------------------------------------------
// pack_inputs / pack_w : unchanged from R10 (validated)
// ---------------------------------------------------------------------------
__global__ __launch_bounds__(256) void pack_inputs(
    const float* __restrict__ Q, const float* __restrict__ K,
    const float* __restrict__ V, float* __restrict__ Ap)
{
    __shared__ float s[128 * 36];
    const int z = blockIdx.z, cx = blockIdx.x, my = blockIdx.y;
    const int tid = threadIdx.x;
    const float* A = z == 0 ? Q : (z == 1 ? K : V);
#pragma unroll
    for (int j = 0; j < 4; j++) {
        const int idx = tid + j * 256;
        const int r = idx >> 3, c4 = (idx & 7) * 4;
        *(float4*)&s[r * 36 + c4] =
            *(const float4*)&A[(size_t)(my * 128 + r) * DM_ + cx * 32 + c4];
    }
    __syncthreads();
    float* dst = Ap + (size_t)z * PLANE_ + ((size_t)my * 32 + cx) * 4096;
#pragma unroll
    for (int j = 0; j < 4; j++) {
        const int ci = tid + j * 256;
        const int kt = ci >> 8, mtg = (ci >> 5) & 7, ln = ci & 31;
        const int r0 = mtg * 16 + (ln >> 2), c0 = kt * 8 + (ln & 3);
        uint4 o;
        o.x = to_tf32(s[r0 * 36 + c0]);
        o.y = to_tf32(s[(r0 + 8) * 36 + c0]);
        o.z = to_tf32(s[r0 * 36 + c0 + 4]);
        o.w = to_tf32(s[(r0 + 8) * 36 + c0 + 4]);
        *(uint4*)&dst[ci * 4] = o;
    }
}

__global__ __launch_bounds__(256) void pack_w(
    const float* __restrict__ Wq, const float* __restrict__ Wk,
    const float* __restrict__ Wv, const float* __restrict__ Wo,
    float* __restrict__ Wp)
{
    __shared__ float s[32 * 132];
    const int z = blockIdx.z, cx = blockIdx.x, nt8 = blockIdx.y;
    const int tid = threadIdx.x;
    if (z < 3) {
        const float* W = z == 0 ? Wq : (z == 1 ? Wk : Wv);
        const int h0 = nt8 * 2;
#pragma unroll
        for (int j = 0; j < 4; j++) {
            const int idx = tid + j * 256;
            const int k = idx >> 5, hi = (idx >> 4) & 1, jj = (idx & 15) * 4;
            *(float4*)&s[k * 132 + hi * 64 + jj] =
                *(const float4*)&W[(size_t)(h0 + hi) * (DM_ * DH_) +
                                   (size_t)(cx * 32 + k) * DH_ + jj];
        }
    } else {
#pragma unroll
        for (int j = 0; j < 4; j++) {
            const int idx = tid + j * 256;
            const int k = idx >> 5, nn = (idx & 31) * 4;
            *(float4*)&s[k * 132 + nn] =
                *(const float4*)&Wo[(size_t)(cx * 32 + k) * DM_ + nt8 * 128 + nn];
        }
    }
    __syncthreads();
    float* dst = Wp + (size_t)z * DM_ * DM_ + ((size_t)nt8 * 32 + cx) * 4096;
#pragma unroll
    for (int j = 0; j < 4; j++) {
        const int ci = tid + j * 256;
        const int kt = ci >> 8, ng = (ci >> 5) & 7, ln = ci & 31;
        const int ke = kt * 8 + (ln & 3), ne = ng * 16 + (ln >> 2);
        uint4 o;
        o.x = to_tf32(s[ke * 132 + ne]);
        o.y = to_tf32(s[(ke + 4) * 132 + ne]);
        o.z = to_tf32(s[ke * 132 + ne + 8]);
        o.w = to_tf32(s[(ke + 4) * 132 + ne + 8]);
        *(uint4*)&dst[ci * 4] = o;
    }
}

// ---------------------------------------------------------------------------
// GEMM (unchanged from R10): both operands fragment-packed.
// mode 0: plain out; 1: Q-plane scatter; 2: K-plane QK-B-packed;
// 3: V-plane PV-B-packed.
// ---------------------------------------------------------------------------
#define STGB 32768
#define GEMM_SMEM (3 * STGB)   // 98304

__device__ __forceinline__ void gemm_body(
    const float* __restrict__ Ap, const float* __restrict__ Bp,
    const float* __restrict__ bias, float* __restrict__ out,
    const int mode, char* smraw, const uint32_t sb)
{
    const int tid = threadIdx.x, lane = tid & 31, wid = tid >> 5;
    const int g = lane >> 2, qd = lane & 3;
    const int wm = wid & 1, wn = wid >> 1;
    const int mtile = blockIdx.y, ntile = blockIdx.x;
    const int m0 = mtile * 128, n0 = ntile * 128;

    const float* Ab = Ap + (size_t)mtile * 32 * 4096;
    const float* Bb = Bp + (size_t)ntile * 32 * 4096;

    float acc[4][4][4];
#pragma unroll
    for (int i = 0; i < 4; i++)
#pragma unroll
        for (int j = 0; j < 4; j++)
#pragma unroll
            for (int k = 0; k < 4; k++) acc[i][j][k] = 0.f;

#define GLOAD(c, s) do {                                                      \
    const uint32_t abase = sb + (s) * STGB;                                   \
    const uint32_t bbase = abase + 16384;                                     \
    const float* asrc = Ab + (size_t)(c) * 4096;                              \
    const float* bsrc = Bb + (size_t)(c) * 4096;                              \
    _Pragma("unroll")                                                         \
    for (int j = 0; j < 4; j++) {                                             \
        const int u = tid + j * 256;                                          \
        CP16(abase + u * 16, asrc + u * 4);                                   \
        CP16(bbase + u * 16, bsrc + u * 4);                                   \
    }                                                                         \
    CP_COMMIT();                                                              \
} while (0)

    GLOAD(0, 0);
    GLOAD(1, 1);

    for (int c = 0; c < 32; c++) {
        const int s = c - (c / 3) * 3;
        int s2 = s + 2; if (s2 >= 3) s2 -= 3;
        CP_WAIT1();
        __syncthreads();
        if (c < 30) GLOAD(c + 2, s2); else CP_COMMIT();

        const uint4* as = (const uint4*)(smraw + s * STGB);
        const uint4* bs = as + 1024;
#pragma unroll
        for (int kt = 0; kt < 4; kt++) {
            uint32_t af[4][4];
#pragma unroll
            for (int mt = 0; mt < 4; mt++) {
                uint4 v = as[(kt * 8 + wm * 4 + mt) * 32 + lane];
                af[mt][0] = v.x; af[mt][1] = v.y; af[mt][2] = v.z; af[mt][3] = v.w;
            }
            uint32_t bf[4][2];
#pragma unroll
            for (int p = 0; p < 2; p++) {
                uint4 v = bs[(kt * 8 + wn * 2 + p) * 32 + lane];
                bf[2 * p][0] = v.x; bf[2 * p][1] = v.y;
                bf[2 * p + 1][0] = v.z; bf[2 * p + 1][1] = v.w;
            }
#pragma unroll
            for (int mt = 0; mt < 4; mt++)
#pragma unroll
                for (int nt = 0; nt < 4; nt++)
                    mma_16n8k8(acc[mt][nt], af[mt], bf[nt]);
        }
    }
#undef GLOAD

#pragma unroll
    for (int mt = 0; mt < 4; mt++) {
#pragma unroll
        for (int nt = 0; nt < 4; nt++) {
            const int mb = m0 + wm * 64 + mt * 16 + g;
            const int nb = n0 + wn * 32 + nt * 8 + 2 * qd;
            if (mode == 0) {
                float2 v01, v23;
                v01.x = acc[mt][nt][0] + bias[nb];
                v01.y = acc[mt][nt][1] + bias[nb + 1];
                v23.x = acc[mt][nt][2] + bias[nb];
                v23.y = acc[mt][nt][3] + bias[nb + 1];
                *(float2*)&out[(size_t)mb * DM_ + nb] = v01;
                *(float2*)&out[(size_t)(mb + 8) * DM_ + nb] = v23;
            } else if (mode == 1) {
                float2 v01, v23;
                v01.x = __uint_as_float(to_tf32(acc[mt][nt][0] + bias[nb]));
                v01.y = __uint_as_float(to_tf32(acc[mt][nt][1] + bias[nb + 1]));
                v23.x = __uint_as_float(to_tf32(acc[mt][nt][2] + bias[nb]));
                v23.y = __uint_as_float(to_tf32(acc[mt][nt][3] + bias[nb + 1]));
                const size_t base = (size_t)(nb >> 6) * ((size_t)BSN_ * DH_) + (nb & 63);
                *(float2*)&out[base + (size_t)mb * DH_] = v01;
                *(float2*)&out[base + (size_t)(mb + 8) * DH_] = v23;
            } else {
#pragma unroll
                for (int e = 0; e < 4; e++) {
                    const int m = mb + ((e & 2) ? 8 : 0);
                    const int n = nb + (e & 1);
                    const float val =
                        __uint_as_float(to_tf32(acc[mt][nt][e] + bias[n]));
                    const int sidx = m & 2047, d = n & 63;
                    const int hb = (n >> 6) * 2 + (m >> 11);
                    const int sl = sidx & 63;
                    const size_t base = (size_t)(hb * 32 + (sidx >> 6)) * 4096;
                    size_t off;
                    if (mode == 2)
                        off = base +
                              (((d >> 3) * 4 + (sl >> 4)) * 32 +
                               (sl & 7) * 4 + (d & 3)) * 4 +
                              ((sl >> 3) & 1) * 2 + ((d >> 2) & 1);
                    else
                        off = base +
                              (((sl >> 3) * 4 + (d >> 4)) * 32 +
                               (d & 7) * 4 + (sl & 3)) * 4 +
                              ((d >> 3) & 1) * 2 + ((sl >> 2) & 1);
                    out[off] = val;
                }
            }
        }
    }
}

__global__ __launch_bounds__(256, 2) void gemm_qkv(
    const float* __restrict__ Apack, const float* __restrict__ Wp,
    const float* __restrict__ b0, const float* __restrict__ b1,
    const float* __restrict__ b2, float* __restrict__ outqkv)
{
    extern __shared__ __align__(16) char smraw[];
    const int z = blockIdx.z;
    const float* bias = z == 0 ? b0 : (z == 1 ? b1 : b2);
    const int mode = z == 0 ? 1 : (z == 1 ? 2 : 3);
    gemm_body(Apack + (size_t)z * PLANE_, Wp + (size_t)z * DM_ * DM_, bias,
              outqkv + (size_t)z * PLANE_, mode, smraw, smem_u32(smraw));
}

__global__ __launch_bounds__(256, 2) void gemm_o(
    const float* __restrict__ Apack, const float* __restrict__ Bp,
    const float* __restrict__ bias, float* __restrict__ out)
{
    extern __shared__ __align__(16) char smraw[];
    gemm_body(Apack, Bp, bias, out, 0, smraw, smem_u32(smraw));
}

// ---------------------------------------------------------------------------
// Flash attention: 128 threads = 4 warps x 32 q-rows. Each K/V B-fragment
// load feeds BOTH 16-row halves (K/V crossbar traffic halved vs R10).
// SMEM floats: stage st @ st*8192: K 4096 | V 4096;  P @ 16384 + wid*2048,
//              half h at +h*1024 (A-fragment chunk layout, 4KB per half).
// ---------------------------------------------------------------------------
#define ATTN_SMEM ((16384 + 4 * 2048) * 4)   // 98304 bytes

__global__ __launch_bounds__(128, 2) void attn_mma(
    const float* __restrict__ Q, const float* __restrict__ K,
    const float* __restrict__ V, float* __restrict__ Op)
{
    extern __shared__ __align__(16) float sm[];
    const uint32_t sb = smem_u32(sm);
    const int tid = threadIdx.x, lane = tid & 31, wid = tid >> 5;  // wid 0..3
    const int g = lane >> 2, qd = lane & 3;
    float* Pw = sm + 16384 + wid * 2048;

    const int hb = blockIdx.y, q0 = blockIdx.x * 128;
    const float* Qg = Q + (size_t)hb * (S_ * DH_);
    const float* Kg = K + (size_t)hb * (S_ * DH_);   // packed plane
    const float* Vg = V + (size_t)hb * (S_ * DH_);

    // Q fragments in registers for both halves (already tf32; *0.125 exact)
    uint32_t qf[2][8][4];
#pragma unroll
    for (int h = 0; h < 2; h++) {
        const float* r0 = Qg + (size_t)(q0 + wid * 32 + h * 16 + g) * DH_ + qd;
        const float* r8 = r0 + 8 * DH_;
#pragma unroll
        for (int kt = 0; kt < 8; kt++) {
            qf[h][kt][0] = __float_as_uint(r0[kt * 8] * 0.125f);
            qf[h][kt][1] = __float_as_uint(r8[kt * 8] * 0.125f);
            qf[h][kt][2] = __float_as_uint(r0[kt * 8 + 4] * 0.125f);
            qf[h][kt][3] = __float_as_uint(r8[kt * 8 + 4] * 0.125f);
        }
    }

#define KVLOAD(t, st) do {                                                    \
    const uint32_t kb = sb + (st) * 32768;                                    \
    const uint32_t vb = kb + 16384;                                           \
    const float* ksrc = Kg + (size_t)(t) * 4096;                              \
    const float* vsrc = Vg + (size_t)(t) * 4096;                              \
    _Pragma("unroll")                                                         \
    for (int j = 0; j < 8; j++) {                                             \
        const int u = tid + j * 128;                                          \
        CP16(kb + u * 16, ksrc + u * 4);                                      \
        CP16(vb + u * 16, vsrc + u * 4);                                      \
    }                                                                         \
    CP_COMMIT();                                                              \
} while (0)

    float accO[2][8][4];
#pragma unroll
    for (int h = 0; h < 2; h++)
#pragma unroll
        for (int nt = 0; nt < 8; nt++)
#pragma unroll
            for (int i = 0; i < 4; i++) accO[h][nt][i] = 0.f;
    float mrow0[2] = {-1e30f, -1e30f}, mrow1[2] = {-1e30f, -1e30f};
    float lrow0[2] = {0.f, 0.f}, lrow1[2] = {0.f, 0.f};

    KVLOAD(0, 0);
    KVLOAD(1, 1);

    for (int t = 0; t < 32; t++) {
        const int st = t & 1;
        CP_WAIT1();
        __syncthreads();
        const uint4* K4 = (const uint4*)(sm + st * 8192);
        const uint4* V4 = (const uint4*)(sm + st * 8192 + 4096);

        // S = (Q/8) K^T for both halves — each K frag load feeds 4 mmas
        float s[2][8][4];
#pragma unroll
        for (int h = 0; h < 2; h++)
#pragma unroll
            for (int nt = 0; nt < 8; nt++)
#pragma unroll
                for (int i = 0; i < 4; i++) s[h][nt][i] = 0.f;
#pragma unroll
        for (int kt = 0; kt < 8; kt++) {
#pragma unroll
            for (int np = 0; np < 4; np++) {
                uint4 v = K4[(kt * 4 + np) * 32 + lane];
                uint32_t b0[2] = {v.x, v.y};
                uint32_t b1[2] = {v.z, v.w};
                mma_16n8k8(s[0][2 * np],     qf[0][kt], b0);
                mma_16n8k8(s[0][2 * np + 1], qf[0][kt], b1);
                mma_16n8k8(s[1][2 * np],     qf[1][kt], b0);
                mma_16n8k8(s[1][2 * np + 1], qf[1][kt], b1);
            }
        }

        // online softmax per half (rows g, g+8; 4-lane row groups)
#pragma unroll
        for (int h = 0; h < 2; h++) {
            float mn0 = mrow0[h], mn1 = mrow1[h];
#pragma unroll
            for (int nt = 0; nt < 8; nt++) {
                mn0 = fmaxf(mn0, fmaxf(s[h][nt][0], s[h][nt][1]));
                mn1 = fmaxf(mn1, fmaxf(s[h][nt][2], s[h][nt][3]));
            }
            mn0 = fmaxf(mn0, __shfl_xor_sync(0xffffffffu, mn0, 1));
            mn0 = fmaxf(mn0, __shfl_xor_sync(0xffffffffu, mn0, 2));
            mn1 = fmaxf(mn1, __shfl_xor_sync(0xffffffffu, mn1, 1));
            mn1 = fmaxf(mn1, __shfl_xor_sync(0xffffffffu, mn1, 2));
            const float c0 = __expf(mrow0[h] - mn0), c1 = __expf(mrow1[h] - mn1);
            mrow0[h] = mn0; mrow1[h] = mn1;
            float rs0 = 0.f, rs1 = 0.f;
#pragma unroll
            for (int nt = 0; nt < 8; nt++) {
                const float p0 = __expf(s[h][nt][0] - mn0);
                const float p1 = __expf(s[h][nt][1] - mn0);
                const float p2 = __expf(s[h][nt][2] - mn1);
                const float p3 = __expf(s[h][nt][3] - mn1);
                rs0 += p0 + p1;
                rs1 += p2 + p3;
                float* ch = Pw + h * 1024 + nt * 128 + g * 16 + ((qd >= 2) ? 2 : 0);
                const int qa = (2 * qd) & 3, qb2 = (2 * qd + 1) & 3;
                ch[qa * 4]      = __uint_as_float(to_tf32(p0));
                ch[qb2 * 4]     = __uint_as_float(to_tf32(p1));
                ch[qa * 4 + 1]  = __uint_as_float(to_tf32(p2));
                ch[qb2 * 4 + 1] = __uint_as_float(to_tf32(p3));
            }
            rs0 += __shfl_xor_sync(0xffffffffu, rs0, 1);
            rs0 += __shfl_xor_sync(0xffffffffu, rs0, 2);
            rs1 += __shfl_xor_sync(0xffffffffu, rs1, 1);
            rs1 += __shfl_xor_sync(0xffffffffu, rs1, 2);
            lrow0[h] = lrow0[h] * c0 + rs0;
            lrow1[h] = lrow1[h] * c1 + rs1;
#pragma unroll
            for (int nt = 0; nt < 8; nt++) {
                accO[h][nt][0] *= c0; accO[h][nt][1] *= c0;
                accO[h][nt][2] *= c1; accO[h][nt][3] *= c1;
            }
        }
        __syncwarp();

        // O += P V — each V frag load feeds 4 mmas (both halves)
        const uint4* P0 = (const uint4*)Pw;
        const uint4* P1 = (const uint4*)(Pw + 1024);
#pragma unroll
        for (int kt = 0; kt < 8; kt++) {
            uint4 a0v = P0[kt * 32 + lane];
            uint4 a1v = P1[kt * 32 + lane];
            uint32_t a0[4] = {a0v.x, a0v.y, a0v.z, a0v.w};
            uint32_t a1[4] = {a1v.x, a1v.y, a1v.z, a1v.w};
#pragma unroll
            for (int np = 0; np < 4; np++) {
                uint4 v = V4[(kt * 4 + np) * 32 + lane];
                uint32_t b0[2] = {v.x, v.y};
                uint32_t b1[2] = {v.z, v.w};
                mma_16n8k8(accO[0][2 * np],     a0, b0);
                mma_16n8k8(accO[0][2 * np + 1], a0, b1);
                mma_16n8k8(accO[1][2 * np],     a1, b0);
                mma_16n8k8(accO[1][2 * np + 1], a1, b1);
            }
        }
        __syncthreads();
        if (t < 30) KVLOAD(t + 2, st); else CP_COMMIT();
    }
#undef KVLOAD

    // Epilogue per half: write fragment-packed A for gemm_o (tf32-rounded).
#pragma unroll
    for (int h = 0; h < 2; h++) {
        const float i0 = 1.f / lrow0[h], i1 = 1.f / lrow1[h];
        const int mrow = 8 * blockIdx.x + wid * 2 + h;   // 16-row group index
        const int mtg = mrow >> 4;
        const int rr = mrow & 15;
        const int halfm = rr >> 3, gfrag = rr & 7;
#pragma unroll
        for (int nt = 0; nt < 8; nt++) {
            float vals[4];
            vals[0] = accO[h][nt][0] * i0;
            vals[1] = accO[h][nt][1] * i0;
            vals[2] = accO[h][nt][2] * i1;
            vals[3] = accO[h][nt][3] * i1;
            const int kbase = g * 64 + nt * 8 + 2 * qd;
#pragma unroll
            for (int e = 0; e < 4; e++) {
                const int k = kbase + (e & 1) + (e >> 1) * 512;
                const int chunk = k >> 5;
                const int kt = (k >> 3) & 3;
                const int q4 = k & 7;
                const int qp = q4 >> 2, qdf = q4 & 3;
                const int lane2 = gfrag * 4 + qdf;
                const int word = halfm + 2 * qp;
                const size_t off = ((size_t)(hb * 32 + chunk)) * 4096 +
                                   ((kt * 8 + mtg) * 32 + lane2) * 4 + word;
                Op[off] = __uint_as_float(to_tf32(vals[e]));
            }
        }
    }
}

// ---------------------------------------------------------------------------
extern "C" void kernel_launch(void* const* d_in, const int* in_sizes, int n_in,
                              void* d_out, int out_size)
{
    const float* query = (const float*)d_in[0];
    const float* key_  = (const float*)d_in[1];
    const float* value = (const float*)d_in[2];
    const float* Wq    = (const float*)d_in[3];
    const float* bq    = (const float*)d_in[4];
    const float* Wk    = (const float*)d_in[5];
    const float* bk    = (const float*)d_in[6];
    const float* Wv    = (const float*)d_in[7];
    const float* bv    = (const float*)d_in[8];
    const float* Wo    = (const float*)d_in[9];
    const float* bo    = (const float*)d_in[10];
    float* out = (float*)d_out;

    float *qkv, *apack, *attp, *wpack;
    cudaGetSymbolAddress((void**)&qkv, g_qkv);
    cudaGetSymbolAddress((void**)&apack, g_apack);
    cudaGetSymbolAddress((void**)&attp, g_attp);
    cudaGetSymbolAddress((void**)&wpack, g_wpack);

    cudaFuncSetAttribute(gemm_qkv, cudaFuncAttributeMaxDynamicSharedMemorySize, GEMM_SMEM);
    cudaFuncSetAttribute(gemm_o, cudaFuncAttributeMaxDynamicSharedMemorySize, GEMM_SMEM);
    cudaFuncSetAttribute(attn_mma, cudaFuncAttributeMaxDynamicSharedMemorySize, ATTN_SMEM);

    pack_w<<<dim3(32, 8, 4), 256>>>(Wq, Wk, Wv, Wo, wpack);
    pack_inputs<<<dim3(32, 32, 3), 256>>>(query, key_, value, apack);

    gemm_qkv<<<dim3(8, 32, 3), 256, GEMM_SMEM>>>(apack, wpack, bq, bk, bv, qkv);

    attn_mma<<<dim3(S_ / 128, HB_), 128, ATTN_SMEM>>>(qkv, qkv + PLANE_,
                                                      qkv + 2 * PLANE_, attp);

    gemm_o<<<dim3(8, 32), 256, GEMM_SMEM>>>(attp, wpack + (size_t)3 * DM_ * DM_,
                                            bo, out);
}